// round 13
// baseline (speedup 1.0000x reference)
#include <cuda_runtime.h>
#include <cuda_bf16.h>
#include <cstdint>

// ShiftLayer: out[b,t,c] = in[b, t+off[c], c], off[c] = {0,-1,+1} for c%3 = {0,1,2},
// zero padding at sequence ends. B=8, L=8192, C=384, fp32.
//
// Quad-row 256-bit kernel: one thread produces FOUR consecutive output rows
// (t..t+3) at one 8-channel slot. It issues 6 independent LDG.256 (rows
// t-1..t+4), routes by the static per-channel residue, and does four STG.256
// with L2::evict_first. Read amplification drops 2x -> 1.5x vs the pair-row
// version (less L1/L2 traffic - the measured trend R10->R12: amp 3->2 gave
// cold 29.2->26.1us), index math per byte halves again, and all load slots
// stay independent (no loop-carried rotation). __launch_bounds__(128,6)
// gives an 85-reg budget so ptxas has slack for the ~60-reg live set and
// cannot re-serialize the loads via a tight register cap (R4 failure mode).

#define B_DIM 8
#define L_DIM 8192
#define C_DIM 384
#define SLOTS (C_DIM / 8)               // 48 float8 slots per row
#define ROWS_PER_THREAD 4
#define THREADS 128

__device__ __forceinline__ void ld8(uint32_t* d, const float* p) {
    asm volatile("ld.global.v8.b32 {%0,%1,%2,%3,%4,%5,%6,%7}, [%8];"
                 : "=r"(d[0]), "=r"(d[1]), "=r"(d[2]), "=r"(d[3]),
                   "=r"(d[4]), "=r"(d[5]), "=r"(d[6]), "=r"(d[7])
                 : "l"(p));
}
__device__ __forceinline__ void st8(float* p, const uint32_t* v) {
    asm volatile("st.global.L2::evict_first.v8.b32 [%0], {%1,%2,%3,%4,%5,%6,%7,%8};"
                 :: "l"(p),
                    "r"(v[0]), "r"(v[1]), "r"(v[2]), "r"(v[3]),
                    "r"(v[4]), "r"(v[5]), "r"(v[6]), "r"(v[7])
                 : "memory");
}

// Component j has channel residue (m + j) % 3; residue 0 -> C, 1 -> P, 2 -> N.
__device__ __forceinline__ void route8(uint32_t* o, const uint32_t* P,
                                       const uint32_t* C, const uint32_t* N,
                                       bool is1, bool is2) {
    #pragma unroll
    for (int j = 0; j < 8; ++j) {
        const int jc = j % 3;
        if (jc == 0)      o[j] = is1 ? P[j] : (is2 ? N[j] : C[j]);
        else if (jc == 1) o[j] = is1 ? N[j] : (is2 ? C[j] : P[j]);
        else              o[j] = is1 ? C[j] : (is2 ? P[j] : N[j]);
    }
}

__global__ __launch_bounds__(THREADS, 6)
void ShiftLayer_66932770341347_kernel(const float* __restrict__ in,
                                      float* __restrict__ out) {
    const int id = blockIdx.x * THREADS + threadIdx.x;   // (row-quad, slot) index

    const int quad = id / SLOTS;                     // b*(L/4) + t/4
    const int s    = id - quad * SLOTS;              // slot 0..47
    const int t    = (quad & (L_DIM / 4 - 1)) * 4;   // row in [0, L), multiple of 4

    // Base channel residue: (8*s) % 3 == (2*s) % 3 (same for all 4 rows)
    const int m = (2 * s) % 3;
    const bool is1 = (m == 1), is2 = (m == 2);

    // Flat element offset of (row t, slot s) in this batch.
    const size_t base = ((size_t)(quad / (L_DIM / 4)) * L_DIM + t) * C_DIM + 8 * s;
    const float* p = in + base;

    // Rows t-1 .. t+4 : A B C D E F.  Interior rows always valid.
    uint32_t A[8], Bv[8], Cv[8], D[8], E[8], F[8];
    ld8(Bv, p);
    ld8(Cv, p + C_DIM);
    ld8(D,  p + 2 * C_DIM);
    ld8(E,  p + 3 * C_DIM);
    if (t > 0) {
        ld8(A, p - C_DIM);
    } else {
        #pragma unroll
        for (int j = 0; j < 8; ++j) A[j] = 0u;
    }
    if (t + ROWS_PER_THREAD < L_DIM) {
        ld8(F, p + 4 * C_DIM);
    } else {
        #pragma unroll
        for (int j = 0; j < 8; ++j) F[j] = 0u;
    }

    float* q = out + base;
    uint32_t o[8];
    route8(o, A,  Bv, Cv, is1, is2);  st8(q,             o);   // row t
    route8(o, Bv, Cv, D,  is1, is2);  st8(q +     C_DIM, o);   // row t+1
    route8(o, Cv, D,  E,  is1, is2);  st8(q + 2 * C_DIM, o);   // row t+2
    route8(o, D,  E,  F,  is1, is2);  st8(q + 3 * C_DIM, o);   // row t+3
}

extern "C" void kernel_launch(void* const* d_in, const int* in_sizes, int n_in,
                              void* d_out, int out_size) {
    const float* mem = (const float*)d_in[0];
    float* out = (float*)d_out;
    (void)in_sizes; (void)n_in; (void)out_size;

    const int total = B_DIM * (L_DIM / ROWS_PER_THREAD) * SLOTS;  // 786432 threads
    const int grid  = total / THREADS;                            // 6144 blocks
    ShiftLayer_66932770341347_kernel<<<grid, THREADS>>>(mem, out);
}